// round 1
// baseline (speedup 1.0000x reference)
#include <cuda_runtime.h>

// Problem shape (fixed by reference)
#define Bb    4
#define T     1024
#define E     512
#define H     8
#define MTOT  (Bb*T)       // 4096 rows (b*t)
#define NPROJ (H*E)        // 4096 cols (h*e)
#define BH    (Bb*H)       // 32 batch-heads

#define NEG_INF (__int_as_float(0xff800000))

// Scratch (device globals — no allocation allowed in kernel_launch)
__device__ float g_q[MTOT * NPROJ];    // 64 MB  (b,t,h,e) pre-scaled by e^-0.25
__device__ float g_k[MTOT * NPROJ];    // 64 MB  pre-scaled by e^-0.25
__device__ float g_v[MTOT * NPROJ];    // 64 MB
__device__ float g_s[(size_t)BH * T * T];  // 128 MB scores / probs
__device__ float g_ao[MTOT * NPROJ];   // 64 MB  attention output (b,t,h*e)

// ---------------------------------------------------------------------------
// Kernel 1: fused QKV projection.  C[m][n] = sum_k x[m][k] * w[n][k]
// x: (4096, 512) row-major; w: (4096, 512) row-major (out, in).
// z selects which of {k,q,v}; q and k are scaled by 512^-0.25.
// ---------------------------------------------------------------------------
__global__ void proj_kernel(const float* __restrict__ x,
                            const float* __restrict__ wk,
                            const float* __restrict__ wq,
                            const float* __restrict__ wv) {
    const int n0 = blockIdx.x * 64;
    const int m0 = blockIdx.y * 64;
    const int z  = blockIdx.z;
    const float* __restrict__ w = (z == 0) ? wk : (z == 1) ? wq : wv;
    float* outp = (z == 0) ? g_k : (z == 1) ? g_q : g_v;
    const float scale = (z == 2) ? 1.0f : 0.21022410381342864f;  // 512^-0.25

    __shared__ float As[64][17];
    __shared__ float Bs[64][17];
    const int tid = threadIdx.x;
    const int ty = tid >> 4, tx = tid & 15;
    float acc[4][4] = {};

    for (int k0 = 0; k0 < E; k0 += 16) {
        #pragma unroll
        for (int i = tid; i < 1024; i += 256) {
            int r = i >> 4, c = i & 15;
            As[r][c] = x[(m0 + r) * E + k0 + c];
            Bs[r][c] = w[(n0 + r) * E + k0 + c];
        }
        __syncthreads();
        #pragma unroll
        for (int kk = 0; kk < 16; ++kk) {
            float a[4], b[4];
            #pragma unroll
            for (int i = 0; i < 4; i++) a[i] = As[ty * 4 + i][kk];
            #pragma unroll
            for (int j = 0; j < 4; j++) b[j] = Bs[tx * 4 + j][kk];
            #pragma unroll
            for (int i = 0; i < 4; i++)
                #pragma unroll
                for (int j = 0; j < 4; j++)
                    acc[i][j] += a[i] * b[j];
        }
        __syncthreads();
    }
    #pragma unroll
    for (int i = 0; i < 4; i++)
        #pragma unroll
        for (int j = 0; j < 4; j++)
            outp[(size_t)(m0 + ty * 4 + i) * NPROJ + n0 + tx * 4 + j] = acc[i][j] * scale;
}

// ---------------------------------------------------------------------------
// Kernel 2: causal scores.  S[bh][tq][tk] = q_bh[tq] . k_bh[tk]  (masked)
// Skips tiles entirely above the diagonal (writes -inf only).
// ---------------------------------------------------------------------------
__global__ void scores_kernel() {
    const int k0 = blockIdx.x * 64;
    const int q0 = blockIdx.y * 64;
    const int bh = blockIdx.z;
    const int b = bh >> 3, h = bh & 7;
    float* __restrict__ S = g_s + (size_t)bh * T * T;
    const int tid = threadIdx.x;
    const int ty = tid >> 4, tx = tid & 15;

    if (k0 > q0 + 63) {  // fully masked tile
        #pragma unroll
        for (int i = 0; i < 4; i++)
            #pragma unroll
            for (int j = 0; j < 4; j++)
                S[(size_t)(q0 + ty * 4 + i) * T + k0 + tx * 4 + j] = NEG_INF;
        return;
    }

    const size_t base = (size_t)b * T * NPROJ + (size_t)h * E;  // (b,·,h,0)
    __shared__ float As[64][17];
    __shared__ float Bs[64][17];
    float acc[4][4] = {};

    for (int kc = 0; kc < E; kc += 16) {
        #pragma unroll
        for (int i = tid; i < 1024; i += 256) {
            int r = i >> 4, c = i & 15;
            As[r][c] = g_q[base + (size_t)(q0 + r) * NPROJ + kc + c];
            Bs[r][c] = g_k[base + (size_t)(k0 + r) * NPROJ + kc + c];
        }
        __syncthreads();
        #pragma unroll
        for (int kk = 0; kk < 16; ++kk) {
            float a[4], bb[4];
            #pragma unroll
            for (int i = 0; i < 4; i++) a[i] = As[ty * 4 + i][kk];
            #pragma unroll
            for (int j = 0; j < 4; j++) bb[j] = Bs[tx * 4 + j][kk];
            #pragma unroll
            for (int i = 0; i < 4; i++)
                #pragma unroll
                for (int j = 0; j < 4; j++)
                    acc[i][j] += a[i] * bb[j];
        }
        __syncthreads();
    }
    #pragma unroll
    for (int i = 0; i < 4; i++) {
        const int tq = q0 + ty * 4 + i;
        #pragma unroll
        for (int j = 0; j < 4; j++) {
            const int tk = k0 + tx * 4 + j;
            S[(size_t)tq * T + tk] = (tk <= tq) ? acc[i][j] : NEG_INF;
        }
    }
}

// ---------------------------------------------------------------------------
// Kernel 3: row softmax over T=1024 entries. One block of 256 per row.
// -inf entries naturally become exp(...) = 0.
// ---------------------------------------------------------------------------
__global__ void softmax_kernel() {
    float* __restrict__ S = g_s + (size_t)blockIdx.x * T;
    const int tid = threadIdx.x;
    __shared__ float red[256];

    float v[4];
    float m = NEG_INF;
    #pragma unroll
    for (int i = 0; i < 4; i++) { v[i] = S[tid + i * 256]; m = fmaxf(m, v[i]); }
    red[tid] = m; __syncthreads();
    for (int s = 128; s > 0; s >>= 1) {
        if (tid < s) red[tid] = fmaxf(red[tid], red[tid + s]);
        __syncthreads();
    }
    m = red[0]; __syncthreads();

    float sum = 0.f;
    #pragma unroll
    for (int i = 0; i < 4; i++) { v[i] = __expf(v[i] - m); sum += v[i]; }
    red[tid] = sum; __syncthreads();
    for (int s = 128; s > 0; s >>= 1) {
        if (tid < s) red[tid] += red[tid + s];
        __syncthreads();
    }
    const float inv = 1.0f / red[0];
    #pragma unroll
    for (int i = 0; i < 4; i++) S[tid + i * 256] = v[i] * inv;
}

// ---------------------------------------------------------------------------
// Kernel 4: AO[bh][tq][e] = sum_tk P[tq][tk] * V[tk][e].  Causal: only
// k-tiles up to the q-tile diagonal contribute (P is 0 above it).
// ---------------------------------------------------------------------------
__global__ void av_kernel() {
    const int n0 = blockIdx.x * 64;   // over E
    const int q0 = blockIdx.y * 64;
    const int bh = blockIdx.z;
    const int b = bh >> 3, h = bh & 7;
    const float* __restrict__ P = g_s + (size_t)bh * T * T;
    const size_t vbase = (size_t)b * T * NPROJ + (size_t)h * E;
    const int tid = threadIdx.x;
    const int ty = tid >> 4, tx = tid & 15;

    __shared__ float As[64][17];
    __shared__ float Bs[16][65];
    float acc[4][4] = {};

    const int kend = q0 + 64;  // keys [0, q0+63] contribute
    for (int kc = 0; kc < kend; kc += 16) {
        #pragma unroll
        for (int i = tid; i < 1024; i += 256) {
            int r = i >> 4, c = i & 15;
            As[r][c] = P[(size_t)(q0 + r) * T + kc + c];
        }
        #pragma unroll
        for (int i = tid; i < 1024; i += 256) {
            int r = i >> 6, c = i & 63;
            Bs[r][c] = g_v[vbase + (size_t)(kc + r) * NPROJ + n0 + c];
        }
        __syncthreads();
        #pragma unroll
        for (int kk = 0; kk < 16; ++kk) {
            float a[4], bb[4];
            #pragma unroll
            for (int i = 0; i < 4; i++) a[i] = As[ty * 4 + i][kk];
            #pragma unroll
            for (int j = 0; j < 4; j++) bb[j] = Bs[kk][tx * 4 + j];
            #pragma unroll
            for (int i = 0; i < 4; i++)
                #pragma unroll
                for (int j = 0; j < 4; j++)
                    acc[i][j] += a[i] * bb[j];
        }
        __syncthreads();
    }
    #pragma unroll
    for (int i = 0; i < 4; i++)
        #pragma unroll
        for (int j = 0; j < 4; j++)
            g_ao[(size_t)(b * T + q0 + ty * 4 + i) * NPROJ + h * E + n0 + tx * 4 + j] = acc[i][j];
}

// ---------------------------------------------------------------------------
// Kernel 5: unify.  out[m][n] = sum_k AO[m][k] * w_u[n][k] + b_u[n]
// ---------------------------------------------------------------------------
__global__ void unify_kernel(const float* __restrict__ wu,
                             const float* __restrict__ bu,
                             float* __restrict__ out) {
    const int n0 = blockIdx.x * 64;   // over E=512
    const int m0 = blockIdx.y * 64;
    const int tid = threadIdx.x;
    const int ty = tid >> 4, tx = tid & 15;

    __shared__ float As[64][17];
    __shared__ float Bs[64][17];
    float acc[4][4] = {};

    for (int k0 = 0; k0 < NPROJ; k0 += 16) {
        #pragma unroll
        for (int i = tid; i < 1024; i += 256) {
            int r = i >> 4, c = i & 15;
            As[r][c] = g_ao[(size_t)(m0 + r) * NPROJ + k0 + c];
            Bs[r][c] = wu[(size_t)(n0 + r) * NPROJ + k0 + c];
        }
        __syncthreads();
        #pragma unroll
        for (int kk = 0; kk < 16; ++kk) {
            float a[4], bb[4];
            #pragma unroll
            for (int i = 0; i < 4; i++) a[i] = As[ty * 4 + i][kk];
            #pragma unroll
            for (int j = 0; j < 4; j++) bb[j] = Bs[tx * 4 + j][kk];
            #pragma unroll
            for (int i = 0; i < 4; i++)
                #pragma unroll
                for (int j = 0; j < 4; j++)
                    acc[i][j] += a[i] * bb[j];
        }
        __syncthreads();
    }
    #pragma unroll
    for (int i = 0; i < 4; i++)
        #pragma unroll
        for (int j = 0; j < 4; j++)
            out[(size_t)(m0 + ty * 4 + i) * E + n0 + tx * 4 + j] =
                acc[i][j] + bu[n0 + tx * 4 + j];
}

// ---------------------------------------------------------------------------
extern "C" void kernel_launch(void* const* d_in, const int* in_sizes, int n_in,
                              void* d_out, int out_size) {
    const float* x  = (const float*)d_in[0];
    const float* wk = (const float*)d_in[1];
    const float* wq = (const float*)d_in[2];
    const float* wv = (const float*)d_in[3];
    const float* wu = (const float*)d_in[4];
    const float* bu = (const float*)d_in[5];
    float* out = (float*)d_out;

    dim3 blk(256);
    proj_kernel<<<dim3(NPROJ / 64, MTOT / 64, 3), blk>>>(x, wk, wq, wv);
    scores_kernel<<<dim3(T / 64, T / 64, BH), blk>>>();
    softmax_kernel<<<BH * T, 256>>>();
    av_kernel<<<dim3(E / 64, T / 64, BH), blk>>>();
    unify_kernel<<<dim3(E / 64, MTOT / 64), blk>>>(wu, bu, out);
}

// round 2
// speedup vs baseline: 2.7254x; 2.7254x over previous
#include <cuda_runtime.h>
#include <cuda_bf16.h>
#include <cstdint>

// Problem shape (fixed)
#define Bb    4
#define T     1024
#define E     512
#define H     8
#define MTOT  (Bb*T)       // 4096
#define NPROJ (H*E)        // 4096
#define BH    (Bb*H)       // 32

#define NEG_INF (__int_as_float(0xff800000))
#define QK_SCALE 0.21022410381342864f   // 512^-0.25

typedef __nv_bfloat16 bf16;

// ---------------- scratch (device globals; no allocs allowed) ----------------
__device__ bf16 g_xh[MTOT * E],   g_xl[MTOT * E];
__device__ bf16 g_wkh[NPROJ * E], g_wkl[NPROJ * E];
__device__ bf16 g_wqh[NPROJ * E], g_wql[NPROJ * E];
__device__ bf16 g_wvh[NPROJ * E], g_wvl[NPROJ * E];
__device__ bf16 g_wuh[E * NPROJ], g_wul[E * NPROJ];
__device__ bf16 g_qh[MTOT * NPROJ], g_ql[MTOT * NPROJ];   // (b,t,h,e), pre-scaled
__device__ bf16 g_kh[MTOT * NPROJ], g_kl[MTOT * NPROJ];   // pre-scaled
__device__ bf16 g_vth[(size_t)BH * E * T], g_vtl[(size_t)BH * E * T]; // (b,h,e,t)
__device__ float g_s[(size_t)BH * T * T];                  // fp32 scores
__device__ bf16 g_ph[(size_t)BH * T * T], g_pl[(size_t)BH * T * T];   // probs
__device__ bf16 g_aoh[MTOT * NPROJ], g_aol[MTOT * NPROJ]; // (b,t,h*e)

// ---------------------------------------------------------------------------
__device__ __forceinline__ void f32split(float x, bf16& h, bf16& l) {
    h = __float2bfloat16(x);
    l = __float2bfloat16(x - __bfloat162float(h));
}

__global__ void split_kernel(const float* __restrict__ src,
                             bf16* __restrict__ h, bf16* __restrict__ l, int n) {
    int i = blockIdx.x * 256 + threadIdx.x;
    if (i < n) f32split(src[i], h[i], l[i]);
}

// ---------------------------------------------------------------------------
// m16n8k16 bf16 mma, fp32 accumulate
__device__ __forceinline__ void mma16816(float* c, const uint32_t* a, const uint32_t* b) {
    asm volatile(
        "mma.sync.aligned.m16n8k16.row.col.f32.bf16.bf16.f32 "
        "{%0,%1,%2,%3}, {%4,%5,%6,%7}, {%8,%9}, {%0,%1,%2,%3};"
        : "+f"(c[0]), "+f"(c[1]), "+f"(c[2]), "+f"(c[3])
        : "r"(a[0]), "r"(a[1]), "r"(a[2]), "r"(a[3]), "r"(b[0]), "r"(b[1]));
}

// ---------------------------------------------------------------------------
// Core: C[128,64] = Ahi/lo[128,K] x Bhi/lo[64,K]^T  (both K-major, bf16x3).
// 256 threads = 8 warps (4 m  x 2 n), warp tile 32x32, mma m16n8k16.
// acc[32]: tile (im in 0..1, jn in 0..3) at acc[(im*4+jn)*4 + r].
// ---------------------------------------------------------------------------
__device__ __forceinline__ void gemm_core(
    const bf16* __restrict__ Ah, const bf16* __restrict__ Al, int lda,
    const bf16* __restrict__ Bh, const bf16* __restrict__ Bl, int ldb,
    int K, float* acc)
{
    __shared__ __align__(16) bf16 sAh[128][40], sAl[128][40];
    __shared__ __align__(16) bf16 sBh[64][40],  sBl[64][40];

    const int tid  = threadIdx.x;
    const int lane = tid & 31;
    const int warp = tid >> 5;
    const int wm = warp >> 1, wn = warp & 1;
    const int g  = lane >> 2, tg = lane & 3;

    const uint32_t* Awh = (const uint32_t*)&sAh[0][0];
    const uint32_t* Awl = (const uint32_t*)&sAl[0][0];
    const uint32_t* Bwh = (const uint32_t*)&sBh[0][0];
    const uint32_t* Bwl = (const uint32_t*)&sBl[0][0];

    #pragma unroll
    for (int i = 0; i < 32; i++) acc[i] = 0.f;

    for (int k0 = 0; k0 < K; k0 += 32) {
        // ---- stage tiles: A 128x32, B 64x32 (uint4 = 8 bf16) ----
        #pragma unroll
        for (int i = tid; i < 512; i += 256) {
            int r = i >> 2, c8 = (i & 3) * 8;
            *(uint4*)&sAh[r][c8] = *(const uint4*)(Ah + (size_t)r * lda + k0 + c8);
            *(uint4*)&sAl[r][c8] = *(const uint4*)(Al + (size_t)r * lda + k0 + c8);
        }
        {
            int r = tid >> 2, c8 = (tid & 3) * 8;
            *(uint4*)&sBh[r][c8] = *(const uint4*)(Bh + (size_t)r * ldb + k0 + c8);
            *(uint4*)&sBl[r][c8] = *(const uint4*)(Bl + (size_t)r * ldb + k0 + c8);
        }
        __syncthreads();

        #pragma unroll
        for (int ks = 0; ks < 2; ks++) {
            uint32_t ah[2][4], al[2][4], bh[4][2], bl[4][2];
            const int w0 = ks * 8 + tg;
            #pragma unroll
            for (int im = 0; im < 2; im++) {
                int r0 = wm * 32 + im * 16 + g;
                ah[im][0] = Awh[r0 * 20 + w0];       ah[im][1] = Awh[(r0 + 8) * 20 + w0];
                ah[im][2] = Awh[r0 * 20 + w0 + 4];   ah[im][3] = Awh[(r0 + 8) * 20 + w0 + 4];
                al[im][0] = Awl[r0 * 20 + w0];       al[im][1] = Awl[(r0 + 8) * 20 + w0];
                al[im][2] = Awl[r0 * 20 + w0 + 4];   al[im][3] = Awl[(r0 + 8) * 20 + w0 + 4];
            }
            #pragma unroll
            for (int jn = 0; jn < 4; jn++) {
                int rn = wn * 32 + jn * 8 + g;
                bh[jn][0] = Bwh[rn * 20 + w0];  bh[jn][1] = Bwh[rn * 20 + w0 + 4];
                bl[jn][0] = Bwl[rn * 20 + w0];  bl[jn][1] = Bwl[rn * 20 + w0 + 4];
            }
            #pragma unroll
            for (int im = 0; im < 2; im++)
                #pragma unroll
                for (int jn = 0; jn < 4; jn++) {
                    float* c = acc + (im * 4 + jn) * 4;
                    mma16816(c, ah[im], bh[jn]);
                    mma16816(c, ah[im], bl[jn]);
                    mma16816(c, al[im], bh[jn]);
                }
        }
        __syncthreads();
    }
}

// epilogue index helpers
#define EPI_FOR \
    const int lane_ = threadIdx.x & 31; \
    const int warp_ = threadIdx.x >> 5; \
    const int wm_ = warp_ >> 1, wn_ = warp_ & 1; \
    const int g_ = lane_ >> 2, tg_ = lane_ & 3; \
    _Pragma("unroll") \
    for (int im = 0; im < 2; im++) \
    _Pragma("unroll") \
    for (int jn = 0; jn < 4; jn++) \
    _Pragma("unroll") \
    for (int r = 0; r < 4; r++)
#define EPI_ROW (wm_ * 32 + im * 16 + g_ + ((r & 2) ? 8 : 0))
#define EPI_COL (wn_ * 32 + jn * 8 + tg_ * 2 + (r & 1))
#define EPI_VAL (acc[(im * 4 + jn) * 4 + r])

// ---------------------------------------------------------------------------
// QKV projection: C[m,n] = x[m,:] . w[n,:];  z: 0=k(scaled) 1=q(scaled) 2=v(->Vt)
// ---------------------------------------------------------------------------
__global__ void proj_kernel() {
    const int n0 = blockIdx.x * 64;
    const int m0 = blockIdx.y * 128;
    const int z  = blockIdx.z;
    const bf16* Wh = (z == 0) ? g_wkh : (z == 1) ? g_wqh : g_wvh;
    const bf16* Wl = (z == 0) ? g_wkl : (z == 1) ? g_wql : g_wvl;
    const float scale = (z == 2) ? 1.0f : QK_SCALE;

    float acc[32];
    gemm_core(g_xh + (size_t)m0 * E, g_xl + (size_t)m0 * E, E,
              Wh + (size_t)n0 * E,  Wl + (size_t)n0 * E,  E, E, acc);

    if (z == 2) {
        // write transposed per-head: vt[b][h][ec][t]
        EPI_FOR {
            int m = m0 + EPI_ROW, n = n0 + EPI_COL;
            int b = m >> 10, t = m & 1023, h = n >> 9, ec = n & 511;
            size_t o = ((size_t)((b * H + h) * E + ec)) * T + t;
            f32split(EPI_VAL, g_vth[o], g_vtl[o]);
        }
    } else {
        bf16* Dh = (z == 0) ? g_kh : g_qh;
        bf16* Dl = (z == 0) ? g_kl : g_ql;
        EPI_FOR {
            size_t o = (size_t)(m0 + EPI_ROW) * NPROJ + n0 + EPI_COL;
            f32split(EPI_VAL * scale, Dh[o], Dl[o]);
        }
    }
}

// ---------------------------------------------------------------------------
// Scores: S[bh][q][k] = q . k ; only lower-triangle tiles computed (no mask —
// softmax ignores k > q).
// ---------------------------------------------------------------------------
__global__ void scores_kernel() {
    const int k0 = blockIdx.x * 64;
    const int q0 = blockIdx.y * 128;
    if (k0 > q0 + 127) return;
    const int bh = blockIdx.z;
    const int b = bh >> 3, h = bh & 7;
    const size_t base = (size_t)b * T * NPROJ + (size_t)h * E;

    float acc[32];
    gemm_core(g_qh + base + (size_t)q0 * NPROJ, g_ql + base + (size_t)q0 * NPROJ, NPROJ,
              g_kh + base + (size_t)k0 * NPROJ, g_kl + base + (size_t)k0 * NPROJ, NPROJ,
              E, acc);

    float* S = g_s + (size_t)bh * T * T;
    EPI_FOR {
        S[(size_t)(q0 + EPI_ROW) * T + k0 + EPI_COL] = EPI_VAL;
    }
}

// ---------------------------------------------------------------------------
// Softmax row: valid keys [0, trow]; writes hi/lo probs, zeros above diagonal.
// ---------------------------------------------------------------------------
__global__ void softmax_kernel() {
    const int row = blockIdx.x;          // 0..BH*T-1
    const int trow = row & 1023;
    const float* __restrict__ S = g_s + (size_t)row * T;
    bf16* __restrict__ Ph = g_ph + (size_t)row * T;
    bf16* __restrict__ Pl = g_pl + (size_t)row * T;
    const int tid = threadIdx.x;
    __shared__ float red[256];

    float v[4];
    float m = NEG_INF;
    #pragma unroll
    for (int i = 0; i < 4; i++) {
        int idx = tid + i * 256;
        v[i] = (idx <= trow) ? S[idx] : NEG_INF;
        m = fmaxf(m, v[i]);
    }
    red[tid] = m; __syncthreads();
    for (int s = 128; s > 0; s >>= 1) {
        if (tid < s) red[tid] = fmaxf(red[tid], red[tid + s]);
        __syncthreads();
    }
    m = red[0]; __syncthreads();

    float sum = 0.f;
    #pragma unroll
    for (int i = 0; i < 4; i++) {
        int idx = tid + i * 256;
        v[i] = (idx <= trow) ? __expf(v[i] - m) : 0.f;
        sum += v[i];
    }
    red[tid] = sum; __syncthreads();
    for (int s = 128; s > 0; s >>= 1) {
        if (tid < s) red[tid] += red[tid + s];
        __syncthreads();
    }
    const float inv = 1.0f / red[0];
    #pragma unroll
    for (int i = 0; i < 4; i++) {
        int idx = tid + i * 256;
        f32split(v[i] * inv, Ph[idx], Pl[idx]);
    }
}

// ---------------------------------------------------------------------------
// AV: AO[bh][q][e] = sum_k P[q][k] V[k][e];  B = Vt (e-major rows, K=t).
// Causal: keys only up to q0+127.
// ---------------------------------------------------------------------------
__global__ void av_kernel() {
    const int n0 = blockIdx.x * 64;    // over E
    const int q0 = blockIdx.y * 128;
    const int bh = blockIdx.z;
    const int b = bh >> 3, h = bh & 7;
    const size_t pbase = (size_t)bh * T * T + (size_t)q0 * T;
    const size_t vbase = (size_t)bh * E * T + (size_t)n0 * T;

    float acc[32];
    gemm_core(g_ph + pbase, g_pl + pbase, T,
              g_vth + vbase, g_vtl + vbase, T,
              q0 + 128, acc);

    EPI_FOR {
        size_t o = (size_t)(b * T + q0 + EPI_ROW) * NPROJ + h * E + n0 + EPI_COL;
        f32split(EPI_VAL, g_aoh[o], g_aol[o]);
    }
}

// ---------------------------------------------------------------------------
// Unify: out[m,n] = AO[m,:] . wu[n,:] + bu[n]
// ---------------------------------------------------------------------------
__global__ void unify_kernel(const float* __restrict__ bu, float* __restrict__ out) {
    const int n0 = blockIdx.x * 64;    // over E
    const int m0 = blockIdx.y * 128;

    float acc[32];
    gemm_core(g_aoh + (size_t)m0 * NPROJ, g_aol + (size_t)m0 * NPROJ, NPROJ,
              g_wuh + (size_t)n0 * NPROJ, g_wul + (size_t)n0 * NPROJ, NPROJ,
              NPROJ, acc);

    EPI_FOR {
        int n = n0 + EPI_COL;
        out[(size_t)(m0 + EPI_ROW) * E + n] = EPI_VAL + bu[n];
    }
}

// ---------------------------------------------------------------------------
extern "C" void kernel_launch(void* const* d_in, const int* in_sizes, int n_in,
                              void* d_out, int out_size) {
    const float* x  = (const float*)d_in[0];
    const float* wk = (const float*)d_in[1];
    const float* wq = (const float*)d_in[2];
    const float* wv = (const float*)d_in[3];
    const float* wu = (const float*)d_in[4];
    const float* bu = (const float*)d_in[5];
    float* out = (float*)d_out;

    bf16 *xh, *xl, *wkh, *wkl, *wqh, *wql, *wvh, *wvl, *wuh, *wul;
    cudaGetSymbolAddress((void**)&xh,  g_xh);  cudaGetSymbolAddress((void**)&xl,  g_xl);
    cudaGetSymbolAddress((void**)&wkh, g_wkh); cudaGetSymbolAddress((void**)&wkl, g_wkl);
    cudaGetSymbolAddress((void**)&wqh, g_wqh); cudaGetSymbolAddress((void**)&wql, g_wql);
    cudaGetSymbolAddress((void**)&wvh, g_wvh); cudaGetSymbolAddress((void**)&wvl, g_wvl);
    cudaGetSymbolAddress((void**)&wuh, g_wuh); cudaGetSymbolAddress((void**)&wul, g_wul);

    const int NE = MTOT * E;   // 2M elements each
    split_kernel<<<NE / 256, 256>>>(x,  xh,  xl,  NE);
    split_kernel<<<NE / 256, 256>>>(wk, wkh, wkl, NE);
    split_kernel<<<NE / 256, 256>>>(wq, wqh, wql, NE);
    split_kernel<<<NE / 256, 256>>>(wv, wvh, wvl, NE);
    split_kernel<<<NE / 256, 256>>>(wu, wuh, wul, NE);

    dim3 blk(256);
    proj_kernel  <<<dim3(NPROJ / 64, MTOT / 128, 3), blk>>>();
    scores_kernel<<<dim3(T / 64, T / 128, BH),        blk>>>();
    softmax_kernel<<<BH * T, 256>>>();
    av_kernel    <<<dim3(E / 64, T / 128, BH),        blk>>>();
    unify_kernel <<<dim3(E / 64, MTOT / 128),         blk>>>(bu, out);
}

// round 4
// speedup vs baseline: 4.1314x; 1.5159x over previous
#include <cuda_runtime.h>
#include <cuda_bf16.h>
#include <cstdint>

// Problem shape (fixed)
#define Bb    4
#define T     1024
#define E     512
#define H     8
#define MTOT  (Bb*T)       // 4096
#define NPROJ (H*E)        // 4096
#define BH    (Bb*H)       // 32

#define NEG_INF (__int_as_float(0xff800000))
#define QK_SCALE 0.21022410381342864f   // 512^-0.25

typedef __nv_bfloat16 bf16;

// ---------------- scratch (device globals; no allocs allowed) ----------------
__device__ __align__(16) bf16 g_xh[MTOT * E],   g_xl[MTOT * E];
__device__ __align__(16) bf16 g_wkh[NPROJ * E], g_wkl[NPROJ * E];
__device__ __align__(16) bf16 g_wqh[NPROJ * E], g_wql[NPROJ * E];
__device__ __align__(16) bf16 g_wvh[NPROJ * E], g_wvl[NPROJ * E];
__device__ __align__(16) bf16 g_wuh[E * NPROJ], g_wul[E * NPROJ];
__device__ __align__(16) bf16 g_qh[MTOT * NPROJ], g_ql[MTOT * NPROJ];  // pre-scaled
__device__ __align__(16) bf16 g_kh[MTOT * NPROJ], g_kl[MTOT * NPROJ];  // pre-scaled
__device__ __align__(16) bf16 g_vth[(size_t)BH * E * T], g_vtl[(size_t)BH * E * T]; // (b,h,e,t)
__device__ float g_s[(size_t)BH * T * T];
__device__ __align__(16) bf16 g_ph[(size_t)BH * T * T], g_pl[(size_t)BH * T * T];
__device__ __align__(16) bf16 g_aoh[MTOT * NPROJ], g_aol[MTOT * NPROJ];

// ---------------------------------------------------------------------------
__device__ __forceinline__ uint32_t smem_u32(const void* p) {
    uint32_t a;
    asm("{ .reg .u64 t; cvta.to.shared.u64 t, %1; cvt.u32.u64 %0, t; }" : "=r"(a) : "l"(p));
    return a;
}
__device__ __forceinline__ void cp16(uint32_t dst, const void* src) {
    asm volatile("cp.async.cg.shared.global [%0], [%1], 16;" :: "r"(dst), "l"(src) : "memory");
}
#define CP_COMMIT()  asm volatile("cp.async.commit_group;" ::: "memory")
#define CP_WAIT(n)   asm volatile("cp.async.wait_group %0;" :: "n"(n) : "memory")

__device__ __forceinline__ void ldsm4(uint32_t* r, uint32_t addr) {
    asm volatile("ldmatrix.sync.aligned.m8n8.x4.shared.b16 {%0,%1,%2,%3}, [%4];"
                 : "=r"(r[0]), "=r"(r[1]), "=r"(r[2]), "=r"(r[3]) : "r"(addr));
}
__device__ __forceinline__ void mma16816(float* c, const uint32_t* a, const uint32_t* b) {
    asm volatile(
        "mma.sync.aligned.m16n8k16.row.col.f32.bf16.bf16.f32 "
        "{%0,%1,%2,%3}, {%4,%5,%6,%7}, {%8,%9}, {%0,%1,%2,%3};"
        : "+f"(c[0]), "+f"(c[1]), "+f"(c[2]), "+f"(c[3])
        : "r"(a[0]), "r"(a[1]), "r"(a[2]), "r"(a[3]), "r"(b[0]), "r"(b[1]));
}

__device__ __forceinline__ void f32split(float x, bf16& h, bf16& l) {
    h = __float2bfloat16(x);
    l = __float2bfloat16(x - __bfloat162float(h));
}

__global__ void split_kernel(const float* __restrict__ src,
                             bf16* __restrict__ h, bf16* __restrict__ l, int n) {
    int i = blockIdx.x * 256 + threadIdx.x;
    if (i < n) f32split(src[i], h[i], l[i]);
}

// ---------------------------------------------------------------------------
// GEMM core: C[128,64] = Ahi/lo[128,K] x Bhi/lo[64,K]^T (K-major, bf16x3).
// 256 threads = 8 warps (4m x 2n), warp tile 32x32, mma m16n8k16.
// Double-buffered cp.async smem + ldmatrix fragment loads (swizzled).
// acc[32]: (im,jn) tile at acc[(im*4+jn)*4 + r].
// ---------------------------------------------------------------------------
// Per-stage layout: Ah 8K | Al 8K | Bh 4K | Bl 4K = 24 KB; 2 stages = 48 KB.
#define ST_AL  8192
#define ST_BH  16384
#define ST_BL  20480
#define STAGE  24576
#define DYN_SMEM (2 * STAGE)

// swizzled byte offset for (row, 16B-group kg) in a [rows][32]bf16 tile (64B rows)
__device__ __forceinline__ uint32_t swz(int row, int kg) {
    return row * 64 + ((kg ^ ((row >> 1) & 3)) << 4);
}

__device__ __forceinline__ void tc_gemm(
    const bf16* __restrict__ Ah, const bf16* __restrict__ Al, int lda,
    const bf16* __restrict__ Bh, const bf16* __restrict__ Bl, int ldb,
    int K, float* acc)
{
    extern __shared__ char sm[];
    const int tid  = threadIdx.x;
    const int lane = tid & 31;
    const int warp = tid >> 5;
    const int wm = warp >> 1, wn = warp & 1;

    // ldmatrix lane->element mapping (see fragment layout of m16n8k16)
    const int arow = ((lane >> 3) & 1) * 8 + (lane & 7);  // A: groups 0,1 rows / 2,3 k+8
    const int akg  = (lane >> 4) & 1;
    const int brow = ((lane >> 4) & 1) * 8 + (lane & 7);  // B: groups 0,1 = k pair, 2,3 = n+8
    const int bkg  = (lane >> 3) & 1;

    #pragma unroll
    for (int i = 0; i < 32; i++) acc[i] = 0.f;

    const int nch = K >> 5;

    // async-load one 32-K chunk into stage (i&1)
    auto load_chunk = [&](int i) {
        const int k0 = i << 5;
        const uint32_t st = smem_u32(sm + (i & 1) * STAGE);
        #pragma unroll
        for (int j = 0; j < 2; j++) {
            int idx = tid + j * 256;            // 512 x 16B for A
            int r = idx >> 2, kg = idx & 3;
            uint32_t o = swz(r, kg);
            cp16(st + o,         Ah + (size_t)r * lda + k0 + kg * 8);
            cp16(st + ST_AL + o, Al + (size_t)r * lda + k0 + kg * 8);
        }
        {
            int r = tid >> 2, kg = tid & 3;     // 256 x 16B for B
            uint32_t o = swz(r, kg);
            cp16(st + ST_BH + o, Bh + (size_t)r * ldb + k0 + kg * 8);
            cp16(st + ST_BL + o, Bl + (size_t)r * ldb + k0 + kg * 8);
        }
        CP_COMMIT();
    };

    load_chunk(0);

    for (int i = 0; i < nch; i++) {
        if (i + 1 < nch) { load_chunk(i + 1); CP_WAIT(1); }
        else             { CP_WAIT(0); }
        __syncthreads();

        const uint32_t st = smem_u32(sm + (i & 1) * STAGE);
        #pragma unroll
        for (int ks = 0; ks < 2; ks++) {
            uint32_t ah[2][4], al[2][4], bh[2][4], bl[2][4];
            #pragma unroll
            for (int im = 0; im < 2; im++) {
                int row = wm * 32 + im * 16 + arow;
                uint32_t o = swz(row, ks * 2 + akg);
                ldsm4(ah[im], st + o);
                ldsm4(al[im], st + ST_AL + o);
            }
            #pragma unroll
            for (int j2 = 0; j2 < 2; j2++) {
                int n = wn * 32 + j2 * 16 + brow;
                uint32_t o = swz(n, ks * 2 + bkg);
                ldsm4(bh[j2], st + ST_BH + o);
                ldsm4(bl[j2], st + ST_BL + o);
            }
            #pragma unroll
            for (int im = 0; im < 2; im++)
                #pragma unroll
                for (int jn = 0; jn < 4; jn++) {
                    float* c = acc + (im * 4 + jn) * 4;
                    const uint32_t* pbh = &bh[jn >> 1][(jn & 1) * 2];
                    const uint32_t* pbl = &bl[jn >> 1][(jn & 1) * 2];
                    mma16816(c, ah[im], pbh);
                    mma16816(c, ah[im], pbl);
                    mma16816(c, al[im], pbh);
                }
        }
        __syncthreads();
    }
}

// epilogue index helpers (m16n8k16 C fragment layout)
#define EPI_FOR \
    const int lane_ = threadIdx.x & 31; \
    const int warp_ = threadIdx.x >> 5; \
    const int wm_ = warp_ >> 1, wn_ = warp_ & 1; \
    const int g_ = lane_ >> 2, tg_ = lane_ & 3; \
    _Pragma("unroll") \
    for (int im = 0; im < 2; im++) \
    _Pragma("unroll") \
    for (int jn = 0; jn < 4; jn++) \
    _Pragma("unroll") \
    for (int r = 0; r < 4; r++)
#define EPI_ROW (wm_ * 32 + im * 16 + g_ + ((r & 2) ? 8 : 0))
#define EPI_COL (wn_ * 32 + jn * 8 + tg_ * 2 + (r & 1))
#define EPI_VAL (acc[(im * 4 + jn) * 4 + r])

// ---------------------------------------------------------------------------
// QKV projection (z: 0=k scaled, 1=q scaled, 2=v -> transposed Vt)
// ---------------------------------------------------------------------------
__global__ __launch_bounds__(256, 2) void proj_kernel() {
    const int n0 = blockIdx.x * 64;
    const int m0 = blockIdx.y * 128;
    const int z  = blockIdx.z;
    const bf16* Wh = (z == 0) ? g_wkh : (z == 1) ? g_wqh : g_wvh;
    const bf16* Wl = (z == 0) ? g_wkl : (z == 1) ? g_wql : g_wvl;
    const float scale = (z == 2) ? 1.0f : QK_SCALE;

    float acc[32];
    tc_gemm(g_xh + (size_t)m0 * E, g_xl + (size_t)m0 * E, E,
            Wh + (size_t)n0 * E,  Wl + (size_t)n0 * E,  E, E, acc);

    if (z == 2) {
        EPI_FOR {
            int m = m0 + EPI_ROW, n = n0 + EPI_COL;
            int b = m >> 10, t = m & 1023, h = n >> 9, ec = n & 511;
            size_t o = ((size_t)((b * H + h) * E + ec)) * T + t;
            f32split(EPI_VAL, g_vth[o], g_vtl[o]);
        }
    } else {
        bf16* Dh = (z == 0) ? g_kh : g_qh;
        bf16* Dl = (z == 0) ? g_kl : g_ql;
        EPI_FOR {
            size_t o = (size_t)(m0 + EPI_ROW) * NPROJ + n0 + EPI_COL;
            f32split(EPI_VAL * scale, Dh[o], Dl[o]);
        }
    }
}

// ---------------------------------------------------------------------------
// Scores: only lower-triangle tiles (softmax ignores k > q)
// ---------------------------------------------------------------------------
__global__ __launch_bounds__(256, 2) void scores_kernel() {
    const int k0 = blockIdx.x * 64;
    const int q0 = blockIdx.y * 128;
    if (k0 >= q0 + 128) return;
    const int bh = blockIdx.z;
    const int b = bh >> 3, h = bh & 7;
    const size_t base = (size_t)b * T * NPROJ + (size_t)h * E;

    float acc[32];
    tc_gemm(g_qh + base + (size_t)q0 * NPROJ, g_ql + base + (size_t)q0 * NPROJ, NPROJ,
            g_kh + base + (size_t)k0 * NPROJ, g_kl + base + (size_t)k0 * NPROJ, NPROJ,
            E, acc);

    float* S = g_s + (size_t)bh * T * T;
    EPI_FOR {
        S[(size_t)(q0 + EPI_ROW) * T + k0 + EPI_COL] = EPI_VAL;
    }
}

// ---------------------------------------------------------------------------
// Softmax row (valid keys [0, trow]); hi/lo probs, zeros above diagonal
// ---------------------------------------------------------------------------
__global__ void softmax_kernel() {
    const int row = blockIdx.x;
    const int trow = row & 1023;
    const float* __restrict__ S = g_s + (size_t)row * T;
    bf16* __restrict__ Ph = g_ph + (size_t)row * T;
    bf16* __restrict__ Pl = g_pl + (size_t)row * T;
    const int tid = threadIdx.x;
    __shared__ float red[256];

    float v[4];
    float m = NEG_INF;
    #pragma unroll
    for (int i = 0; i < 4; i++) {
        int idx = tid + i * 256;
        v[i] = (idx <= trow) ? S[idx] : NEG_INF;
        m = fmaxf(m, v[i]);
    }
    red[tid] = m; __syncthreads();
    for (int s = 128; s > 0; s >>= 1) {
        if (tid < s) red[tid] = fmaxf(red[tid], red[tid + s]);
        __syncthreads();
    }
    m = red[0]; __syncthreads();

    float sum = 0.f;
    #pragma unroll
    for (int i = 0; i < 4; i++) {
        int idx = tid + i * 256;
        v[i] = (idx <= trow) ? __expf(v[i] - m) : 0.f;
        sum += v[i];
    }
    red[tid] = sum; __syncthreads();
    for (int s = 128; s > 0; s >>= 1) {
        if (tid < s) red[tid] += red[tid + s];
        __syncthreads();
    }
    const float inv = 1.0f / red[0];
    #pragma unroll
    for (int i = 0; i < 4; i++) {
        int idx = tid + i * 256;
        f32split(v[i] * inv, Ph[idx], Pl[idx]);
    }
}

// ---------------------------------------------------------------------------
// AV: AO = P @ V (B operand is Vt, K = t truncated causally)
// ---------------------------------------------------------------------------
__global__ __launch_bounds__(256, 2) void av_kernel() {
    const int n0 = blockIdx.x * 64;    // over E
    const int q0 = blockIdx.y * 128;
    const int bh = blockIdx.z;
    const int b = bh >> 3, h = bh & 7;
    const size_t pbase = (size_t)bh * T * T + (size_t)q0 * T;
    const size_t vbase = (size_t)bh * E * T + (size_t)n0 * T;

    float acc[32];
    tc_gemm(g_ph + pbase, g_pl + pbase, T,
            g_vth + vbase, g_vtl + vbase, T,
            q0 + 128, acc);

    EPI_FOR {
        size_t o = (size_t)(b * T + q0 + EPI_ROW) * NPROJ + h * E + n0 + EPI_COL;
        f32split(EPI_VAL, g_aoh[o], g_aol[o]);
    }
}

// ---------------------------------------------------------------------------
// Unify: out = AO @ wu^T + bu
// ---------------------------------------------------------------------------
__global__ __launch_bounds__(256, 2) void unify_kernel(const float* __restrict__ bu,
                                                       float* __restrict__ out) {
    const int n0 = blockIdx.x * 64;    // over E
    const int m0 = blockIdx.y * 128;

    float acc[32];
    tc_gemm(g_aoh + (size_t)m0 * NPROJ, g_aol + (size_t)m0 * NPROJ, NPROJ,
            g_wuh + (size_t)n0 * NPROJ, g_wul + (size_t)n0 * NPROJ, NPROJ,
            NPROJ, acc);

    EPI_FOR {
        int n = n0 + EPI_COL;
        out[(size_t)(m0 + EPI_ROW) * E + n] = EPI_VAL + bu[n];
    }
}

// ---------------------------------------------------------------------------
extern "C" void kernel_launch(void* const* d_in, const int* in_sizes, int n_in,
                              void* d_out, int out_size) {
    const float* x  = (const float*)d_in[0];
    const float* wk = (const float*)d_in[1];
    const float* wq = (const float*)d_in[2];
    const float* wv = (const float*)d_in[3];
    const float* wu = (const float*)d_in[4];
    const float* bu = (const float*)d_in[5];
    float* out = (float*)d_out;

    bf16 *xh, *xl, *wkh, *wkl, *wqh, *wql, *wvh, *wvl, *wuh, *wul;
    cudaGetSymbolAddress((void**)&xh,  g_xh);  cudaGetSymbolAddress((void**)&xl,  g_xl);
    cudaGetSymbolAddress((void**)&wkh, g_wkh); cudaGetSymbolAddress((void**)&wkl, g_wkl);
    cudaGetSymbolAddress((void**)&wqh, g_wqh); cudaGetSymbolAddress((void**)&wql, g_wql);
    cudaGetSymbolAddress((void**)&wvh, g_wvh); cudaGetSymbolAddress((void**)&wvl, g_wvl);
    cudaGetSymbolAddress((void**)&wuh, g_wuh); cudaGetSymbolAddress((void**)&wul, g_wul);

    cudaFuncSetAttribute(proj_kernel,   cudaFuncAttributeMaxDynamicSharedMemorySize, DYN_SMEM);
    cudaFuncSetAttribute(scores_kernel, cudaFuncAttributeMaxDynamicSharedMemorySize, DYN_SMEM);
    cudaFuncSetAttribute(av_kernel,     cudaFuncAttributeMaxDynamicSharedMemorySize, DYN_SMEM);
    cudaFuncSetAttribute(unify_kernel,  cudaFuncAttributeMaxDynamicSharedMemorySize, DYN_SMEM);

    const int NE = MTOT * E;
    split_kernel<<<NE / 256, 256>>>(x,  xh,  xl,  NE);
    split_kernel<<<NE / 256, 256>>>(wk, wkh, wkl, NE);
    split_kernel<<<NE / 256, 256>>>(wq, wqh, wql, NE);
    split_kernel<<<NE / 256, 256>>>(wv, wvh, wvl, NE);
    split_kernel<<<NE / 256, 256>>>(wu, wuh, wul, NE);

    proj_kernel  <<<dim3(NPROJ / 64, MTOT / 128, 3), 256, DYN_SMEM>>>();
    scores_kernel<<<dim3(T / 64, T / 128, BH),        256, DYN_SMEM>>>();
    softmax_kernel<<<BH * T, 256>>>();
    av_kernel    <<<dim3(E / 64, T / 128, BH),        256, DYN_SMEM>>>();
    unify_kernel <<<dim3(E / 64, MTOT / 128),         256, DYN_SMEM>>>(bu, out);
}